// round 3
// baseline (speedup 1.0000x reference)
#include <cuda_runtime.h>
#include <cuda_bf16.h>

// FeatureVectorInteractions: B=4096, N=128, D=64
// out[b] = < sum_i [VI0[b,i]>0] * V0[b,i,:] , sum_j [VI1[b,j]>0] * V1[b,j,:] >
//
// HBM-bound streaming reduction (~272 MB read). One CTA per batch element.
// 256 threads = 16 row-groups (g) x 16 d-quads (q).
//
// R3 changes vs R2 (45.1us, DRAM 75.7%):
//  - masks staged cooperatively into smem (1 scalar LDG/thread instead of 16)
//    -> halves L1tex wavefront-queue occupancy from LDG instructions
//  - phase-split: stream all of V0, then all of V1 (longer sequential spans
//    per CTA -> better DRAM row-buffer locality)

#define NROWS 128
#define DDIM  64
#define DQ    16   // float4s per row
#define GROUPS 16
#define RPG   8    // rows per thread-group per tensor

__global__ __launch_bounds__(256, 8)
void fvi_kernel(const int* __restrict__ VI0,
                const int* __restrict__ VI1,
                const float* __restrict__ V0,
                const float* __restrict__ V1,
                float* __restrict__ out,
                int B)
{
    __shared__ float sm0[NROWS];
    __shared__ float sm1[NROWS];
    __shared__ float4 s0[GROUPS][DQ];   // [g][q] partials
    __shared__ float4 s1[GROUPS][DQ];
    __shared__ float sp[DDIM];

    const int t = threadIdx.x;
    const int g = t >> 4;    // row group 0..15
    const int q = t & 15;    // d-quad   0..15

    for (int b = blockIdx.x; b < B; b += gridDim.x) {
        // ---- Stage 0: cooperative mask staging (1 LDG per thread) ----
        if (t < NROWS) {
            sm0[t] = (__ldg(&VI0[(size_t)b * NROWS + t]) > 0) ? 1.0f : 0.0f;
        } else {
            const int r = t - NROWS;
            sm1[r] = (__ldg(&VI1[(size_t)b * NROWS + r]) > 0) ? 1.0f : 0.0f;
        }
        __syncthreads();

        const float4* __restrict__ v0 =
            reinterpret_cast<const float4*>(V0) + (size_t)b * (NROWS * DQ);
        const float4* __restrict__ v1 =
            reinterpret_cast<const float4*>(V1) + (size_t)b * (NROWS * DQ);

        // ---- Phase 1: stream V0 tile (32KB, sequential in time) ----
        float4 a0 = make_float4(0.f, 0.f, 0.f, 0.f);
        #pragma unroll
        for (int k = 0; k < RPG; ++k) {
            const int i = g + k * GROUPS;            // step k covers rows 16k..16k+15
            const float4 x = __ldg(&v0[i * DQ + q]); // 16 lanes = one 256B row
            const float m = sm0[i];                  // LDS broadcast
            a0.x = fmaf(m, x.x, a0.x);
            a0.y = fmaf(m, x.y, a0.y);
            a0.z = fmaf(m, x.z, a0.z);
            a0.w = fmaf(m, x.w, a0.w);
        }

        // ---- Phase 2: stream V1 tile ----
        float4 a1 = make_float4(0.f, 0.f, 0.f, 0.f);
        #pragma unroll
        for (int k = 0; k < RPG; ++k) {
            const int i = g + k * GROUPS;
            const float4 x = __ldg(&v1[i * DQ + q]);
            const float m = sm1[i];
            a1.x = fmaf(m, x.x, a1.x);
            a1.y = fmaf(m, x.y, a1.y);
            a1.z = fmaf(m, x.z, a1.z);
            a1.w = fmaf(m, x.w, a1.w);
        }

        // ---- Stage 1: park per-(group, dquad) partials ----
        s0[g][q] = a0;
        s1[g][q] = a1;
        __syncthreads();

        // ---- Stage 2: threads 0..63 each own one d-lane; sum groups, u0*u1 ----
        if (t < DDIM) {
            const int dq = t >> 2;
            const int dl = t & 3;
            float u0 = 0.f, u1 = 0.f;
            #pragma unroll
            for (int gg = 0; gg < GROUPS; ++gg) {
                u0 += reinterpret_cast<const float*>(&s0[gg][dq])[dl];
                u1 += reinterpret_cast<const float*>(&s1[gg][dq])[dl];
            }
            sp[t] = u0 * u1;
        }
        __syncthreads();

        // ---- Stage 3: dot-reduce 64 products ----
        if (t < 32) {
            float v = sp[t] + sp[t + 32];
            #pragma unroll
            for (int off = 16; off > 0; off >>= 1)
                v += __shfl_down_sync(0xFFFFFFFFu, v, off);
            if (t == 0) out[b] = v;
        }
        __syncthreads();   // protect smem reuse across grid-stride iterations
    }
}

extern "C" void kernel_launch(void* const* d_in, const int* in_sizes, int n_in,
                              void* d_out, int out_size)
{
    const int*   VI0 = (const int*)d_in[0];
    const int*   VI1 = (const int*)d_in[1];
    const float* V0  = (const float*)d_in[2];
    const float* V1  = (const float*)d_in[3];
    float* out = (float*)d_out;

    const int B = in_sizes[0] / NROWS;  // 4096 for this problem
    fvi_kernel<<<B, 256>>>(VI0, VI1, V0, V1, out, B);
}

// round 4
// speedup vs baseline: 1.0064x; 1.0064x over previous
#include <cuda_runtime.h>
#include <cuda_bf16.h>

// FeatureVectorInteractions: B=4096, N=128, D=64
// out[b] = < sum_i [VI0[b,i]>0] * V0[b,i,:] , sum_j [VI1[b,j]>0] * V1[b,j,:] >
//
// HBM-bound streaming reduction (~272 MB read).
// R4 change vs R3 (45.3us, DRAM 74.9%): balanced resident grid.
//   grid=1024 (B/4), each CTA grid-strides over exactly 4 batches ->
//   single co-resident wave (1024 < 148*8=1184), no partial-wave tail.
//   Previous grid=4096 ran 3.46 waves; the 46%-full last wave idled DRAM.

#define NROWS 128
#define DDIM  64
#define DQ    16   // float4s per row
#define GROUPS 16
#define RPG   8    // rows per thread-group per tensor

__global__ __launch_bounds__(256, 8)
void fvi_kernel(const int* __restrict__ VI0,
                const int* __restrict__ VI1,
                const float* __restrict__ V0,
                const float* __restrict__ V1,
                float* __restrict__ out,
                int B)
{
    __shared__ float sm0[NROWS];
    __shared__ float sm1[NROWS];
    __shared__ float4 s0[GROUPS][DQ];   // [g][q] partials
    __shared__ float4 s1[GROUPS][DQ];
    __shared__ float sp[DDIM];

    const int t = threadIdx.x;
    const int g = t >> 4;    // row group 0..15
    const int q = t & 15;    // d-quad   0..15

    for (int b = blockIdx.x; b < B; b += gridDim.x) {
        // ---- Stage 0: cooperative mask staging (1 LDG per thread) ----
        if (t < NROWS) {
            sm0[t] = (__ldg(&VI0[(size_t)b * NROWS + t]) > 0) ? 1.0f : 0.0f;
        } else {
            const int r = t - NROWS;
            sm1[r] = (__ldg(&VI1[(size_t)b * NROWS + r]) > 0) ? 1.0f : 0.0f;
        }
        __syncthreads();

        const float4* __restrict__ v0 =
            reinterpret_cast<const float4*>(V0) + (size_t)b * (NROWS * DQ);
        const float4* __restrict__ v1 =
            reinterpret_cast<const float4*>(V1) + (size_t)b * (NROWS * DQ);

        // ---- Phase 1: stream V0 tile (32KB) ----
        float4 a0 = make_float4(0.f, 0.f, 0.f, 0.f);
        #pragma unroll
        for (int k = 0; k < RPG; ++k) {
            const int i = g + k * GROUPS;            // step k covers rows 16k..16k+15
            const float4 x = __ldg(&v0[i * DQ + q]); // 16 lanes = one 256B row
            const float m = sm0[i];                  // LDS broadcast
            a0.x = fmaf(m, x.x, a0.x);
            a0.y = fmaf(m, x.y, a0.y);
            a0.z = fmaf(m, x.z, a0.z);
            a0.w = fmaf(m, x.w, a0.w);
        }

        // ---- Phase 2: stream V1 tile ----
        float4 a1 = make_float4(0.f, 0.f, 0.f, 0.f);
        #pragma unroll
        for (int k = 0; k < RPG; ++k) {
            const int i = g + k * GROUPS;
            const float4 x = __ldg(&v1[i * DQ + q]);
            const float m = sm1[i];
            a1.x = fmaf(m, x.x, a1.x);
            a1.y = fmaf(m, x.y, a1.y);
            a1.z = fmaf(m, x.z, a1.z);
            a1.w = fmaf(m, x.w, a1.w);
        }

        // ---- Stage 1: park per-(group, dquad) partials ----
        s0[g][q] = a0;
        s1[g][q] = a1;
        __syncthreads();

        // ---- Stage 2: threads 0..63 each own one d-lane; sum groups, u0*u1 ----
        if (t < DDIM) {
            const int dq = t >> 2;
            const int dl = t & 3;
            float u0 = 0.f, u1 = 0.f;
            #pragma unroll
            for (int gg = 0; gg < GROUPS; ++gg) {
                u0 += reinterpret_cast<const float*>(&s0[gg][dq])[dl];
                u1 += reinterpret_cast<const float*>(&s1[gg][dq])[dl];
            }
            sp[t] = u0 * u1;
        }
        __syncthreads();

        // ---- Stage 3: dot-reduce 64 products ----
        if (t < 32) {
            float v = sp[t] + sp[t + 32];
            #pragma unroll
            for (int off = 16; off > 0; off >>= 1)
                v += __shfl_down_sync(0xFFFFFFFFu, v, off);
            if (t == 0) out[b] = v;
        }
        __syncthreads();   // protect smem reuse across grid-stride iterations
    }
}

extern "C" void kernel_launch(void* const* d_in, const int* in_sizes, int n_in,
                              void* d_out, int out_size)
{
    const int*   VI0 = (const int*)d_in[0];
    const int*   VI1 = (const int*)d_in[1];
    const float* V0  = (const float*)d_in[2];
    const float* V1  = (const float*)d_in[3];
    float* out = (float*)d_out;

    const int B = in_sizes[0] / NROWS;  // 4096 for this problem

    // Balanced resident grid: largest divisor of B that fits in one wave
    // (148 SMs x 8 CTAs = 1184 co-resident CTAs).
    int grid = B;
    for (int cand = 1024; cand >= 1; cand >>= 1) {
        if (cand <= 1184 && B % cand == 0) { grid = cand; break; }
    }

    fvi_kernel<<<grid, 256>>>(VI0, VI1, V0, V1, out, B);
}